// round 1
// baseline (speedup 1.0000x reference)
#include <cuda_runtime.h>
#include <cuda_bf16.h>

// CubEcc2d: Euler characteristic curve of sublevel cubical complex.
// x: [B=32, C=16, H=128, W=128] f32  ->  out: [B,C,RES=64] f32
//
// Strategy: one block per (b,c) image. Per-thread privatized int histograms
// in shared memory (no atomics). Each warp owns 32 columns and sweeps rows
// with a sliding window; each vertex (a,b) emits its 4 incident cells:
//   vertex  (+1): F = v
//   h-edge  (-1): F = max(v, right)           [b < 127]
//   v-edge  (-1): F = max(v, down)            [a < 127]
//   face    (+1): F = max(v, right, down, dg) [a<127 && b<127]
// bin t = clip(ceil(F*63), 0, 63); contribution gated by (F <= 1.0f).

#define NT 128
#define RES 64

__global__ __launch_bounds__(NT)
void cub_ecc_kernel(const float* __restrict__ x, float* __restrict__ out)
{
    __shared__ int hist[RES * NT];      // 32 KB, hist[t*NT + tid]
    __shared__ int partial[2][RES];
    __shared__ int scanbuf[RES];

    const int tid = threadIdx.x;

    // zero private histograms
    #pragma unroll
    for (int i = tid; i < RES * NT; i += NT) hist[i] = 0;
    __syncthreads();

    const float* __restrict__ img = x + (size_t)blockIdx.x * (128 * 128);

    const int lane = tid & 31;
    const int w    = tid >> 5;          // warp id: column block
    const int b    = (w << 5) + lane;   // this thread's column, 0..127
    const bool hasr = (b < 127);

    int* __restrict__ hcol = hist + tid;   // private column

    // sliding window: v = x[a][b], r = x[a][b+1]
    float v = img[b];
    float r = hasr ? img[b + 1] : 0.0f;

    #pragma unroll 2
    for (int a = 0; a < 128; a++) {
        const bool hasd = (a < 127);
        const float* nrow = img + (a + 1) * 128;
        float nv = hasd ? nrow[b] : 0.0f;                 // x[a+1][b]
        float nr = (hasd && hasr) ? nrow[b + 1] : 0.0f;   // x[a+1][b+1]

        // vertex (+1)
        {
            float F = v;
            int t = min(63, max(0, __float2int_ru(F * 63.0f)));
            hcol[t * NT] += (F <= 1.0f) ? 1 : 0;
        }
        // horizontal edge (-1)
        float eh = fmaxf(v, r);
        {
            int t = min(63, max(0, __float2int_ru(eh * 63.0f)));
            hcol[t * NT] -= (hasr && eh <= 1.0f) ? 1 : 0;
        }
        // vertical edge (-1)
        float ev = fmaxf(v, nv);
        {
            int t = min(63, max(0, __float2int_ru(ev * 63.0f)));
            hcol[t * NT] -= (hasd && ev <= 1.0f) ? 1 : 0;
        }
        // face (+1)
        float fc = fmaxf(eh, fmaxf(nv, nr));
        {
            int t = min(63, max(0, __float2int_ru(fc * 63.0f)));
            hcol[t * NT] += (hasr && hasd && fc <= 1.0f) ? 1 : 0;
        }

        v = nv;
        r = nr;
    }
    __syncthreads();

    // ---- reduce 128 private histograms -> 64 totals (skewed, conflict-free)
    {
        const int bin = tid & 63;
        const int p   = tid >> 6;       // 0 or 1: which half of the columns
        int sum = 0;
        #pragma unroll
        for (int i = 0; i < 64; i++) {
            int c = (p << 6) + ((i + bin) & 63);   // skew by bin -> distinct banks
            sum += hist[bin * NT + c];
        }
        partial[p][bin] = sum;
    }
    __syncthreads();

    if (tid < 64) scanbuf[tid] = partial[0][tid] + partial[1][tid];
    __syncthreads();

    // ---- inclusive scan over 64 bins (Hillis-Steele)
    #pragma unroll
    for (int s = 1; s < 64; s <<= 1) {
        int val = 0;
        if (tid < 64) {
            val = scanbuf[tid];
            if (tid >= s) val += scanbuf[tid - s];
        }
        __syncthreads();
        if (tid < 64) scanbuf[tid] = val;
        __syncthreads();
    }

    if (tid < 64) out[blockIdx.x * 64 + tid] = (float)scanbuf[tid];
}

extern "C" void kernel_launch(void* const* d_in, const int* in_sizes, int n_in,
                              void* d_out, int out_size)
{
    const float* x = (const float*)d_in[0];
    float* out = (float*)d_out;
    // 32*16 = 512 images, one block each
    cub_ecc_kernel<<<512, NT>>>(x, out);
}

// round 2
// speedup vs baseline: 1.0428x; 1.0428x over previous
#include <cuda_runtime.h>
#include <cuda_bf16.h>

// CubEcc2d: Euler characteristic curve of sublevel cubical complex.
// x: [B=32, C=16, H=128, W=128] f32  ->  out: [B,C,RES=64] f32
//
// R2: grid was the occupancy limiter (512 blocks = 21% occ). Now 4 row-strips
// per image -> 2048 blocks. Per-thread privatized histograms packed as
// {pos,neg} byte counters, 2 bins per u32 word -> 16KB smem/block.
// Strip partials -> global scratch -> tiny combine+scan kernel.

#define NT 128
#define RES 64
#define STRIPS 4
#define SROWS 32          // rows of vertices per strip

__device__ int g_part[512 * STRIPS * RES];   // strip partial histograms

__global__ __launch_bounds__(NT, 8)
void strip_kernel(const float* __restrict__ x)
{
    // hist word [pair*NT + tid]: bytes = {b0:pos(2p), b1:neg(2p), b2:pos(2p+1), b3:neg(2p+1)}
    __shared__ unsigned int hist[(RES / 2) * NT];   // 16 KB
    __shared__ int red[2][RES];

    const int tid = threadIdx.x;

    #pragma unroll
    for (int i = tid; i < (RES / 2) * NT; i += NT) hist[i] = 0u;
    __syncthreads();

    const int img   = blockIdx.x >> 2;
    const int strip = blockIdx.x & 3;
    const int a0    = strip * SROWS;
    const float* __restrict__ im = x + (size_t)img * (128 * 128);

    const int b = tid;                  // column 0..127
    const bool hasr = (b < 127);

    unsigned int* __restrict__ hcol = hist + tid;   // bank = tid%32, conflict-free

    // sliding window: v = x[a][b], r = x[a][b+1]
    float v = im[a0 * 128 + b];
    float r = hasr ? im[a0 * 128 + b + 1] : 0.0f;

    #pragma unroll 4
    for (int a = a0; a < a0 + SROWS; a++) {
        const bool hasd = (a < 127);
        const float* nrow = im + (a + 1) * 128;
        float nv = hasd ? nrow[b] : 0.0f;
        float nr = (hasd && hasr) ? nrow[b + 1] : 0.0f;

        // vertex (+)
        {
            int t = min(63, max(0, __float2int_ru(v * 63.0f)));
            unsigned add = (v <= 1.0f) ? (1u << ((t & 1) * 16)) : 0u;
            hcol[(t >> 1) * NT] += add;
        }
        // horizontal edge (-)
        float eh = fmaxf(v, r);
        {
            int t = min(63, max(0, __float2int_ru(eh * 63.0f)));
            unsigned add = (hasr && eh <= 1.0f) ? (256u << ((t & 1) * 16)) : 0u;
            hcol[(t >> 1) * NT] += add;
        }
        // vertical edge (-)
        float ev = fmaxf(v, nv);
        {
            int t = min(63, max(0, __float2int_ru(ev * 63.0f)));
            unsigned add = (hasd && ev <= 1.0f) ? (256u << ((t & 1) * 16)) : 0u;
            hcol[(t >> 1) * NT] += add;
        }
        // face (+)
        float fc = fmaxf(eh, fmaxf(nv, nr));
        {
            int t = min(63, max(0, __float2int_ru(fc * 63.0f)));
            unsigned add = (hasr && hasd && fc <= 1.0f) ? (1u << ((t & 1) * 16)) : 0u;
            hcol[(t >> 1) * NT] += add;
        }

        v = nv;
        r = nr;
    }
    __syncthreads();

    // reduce 128 private columns -> 64 bins (skewed, conflict-free)
    {
        const int bin = tid & 63;
        const int p   = tid >> 6;
        const int sh  = (bin & 1) * 16;
        const unsigned int* __restrict__ row = hist + (bin >> 1) * NT;
        int sum = 0;
        #pragma unroll 8
        for (int i = 0; i < 64; i++) {
            int c = (p << 6) + ((i + bin) & 63);
            unsigned w = row[c];
            sum += (int)((w >> sh) & 0xFFu) - (int)((w >> (sh + 8)) & 0xFFu);
        }
        red[p][bin] = sum;
    }
    __syncthreads();

    if (tid < RES)
        g_part[blockIdx.x * RES + tid] = red[0][tid] + red[1][tid];
}

__global__ __launch_bounds__(RES)
void final_kernel(float* __restrict__ out)
{
    __shared__ int s[RES];
    const int img = blockIdx.x;
    const int t = threadIdx.x;

    int sum = 0;
    #pragma unroll
    for (int k = 0; k < STRIPS; k++)
        sum += g_part[(img * STRIPS + k) * RES + t];
    s[t] = sum;
    __syncthreads();

    // inclusive scan over 64 bins
    #pragma unroll
    for (int st = 1; st < RES; st <<= 1) {
        int v = s[t];
        if (t >= st) v += s[t - st];
        __syncthreads();
        s[t] = v;
        __syncthreads();
    }

    out[img * RES + t] = (float)s[t];
}

extern "C" void kernel_launch(void* const* d_in, const int* in_sizes, int n_in,
                              void* d_out, int out_size)
{
    const float* x = (const float*)d_in[0];
    float* out = (float*)d_out;
    strip_kernel<<<512 * STRIPS, NT>>>(x);
    final_kernel<<<512, RES>>>(out);
}

// round 3
// speedup vs baseline: 1.4675x; 1.4072x over previous
#include <cuda_runtime.h>
#include <cuda_bf16.h>

// CubEcc2d: Euler characteristic curve of sublevel cubical complex.
// x: [B=32, C=16, H=128, W=128] f32  ->  out: [B,C,RES=64] f32
//
// R3: plain u32 signed per-thread counters (4-instr RMW), bin-domain sliding
// window (2 float->int per vertex, edges/faces via integer max), loop-invariant
// boundary gating, lean shuffle-scan final kernel.

#define NT 128
#define RES 64
#define STRIPS 4
#define SROWS 32

__device__ int g_part[512 * STRIPS * RES];

__global__ __launch_bounds__(NT, 7)
void strip_kernel(const float* __restrict__ x)
{
    __shared__ int hist[RES * NT];          // 32 KB, hist[t*128 + tid]
    const int tid = threadIdx.x;

    #pragma unroll
    for (int i = tid; i < RES * NT; i += NT) hist[i] = 0;
    __syncthreads();

    const int img   = blockIdx.x >> 2;
    const int strip = blockIdx.x & 3;
    const int a0    = strip * SROWS;
    const float* __restrict__ im = x + (size_t)img * (128 * 128);

    const int b   = tid;
    const int bp1 = min(b + 1, 127);        // lane 127: r = v (adds gated off)
    const int valH = (b < 127) ? -1 : 0;    // h-edge sign, loop-invariant
    const int valF = (b < 127) ?  1 : 0;    // face sign, loop-invariant

    int* __restrict__ hcol = hist + tid;    // bank = tid%32, conflict-free

    // seed: bins of row a0
    float v = im[a0 * 128 + b];
    float r = im[a0 * 128 + bp1];
    int tv = min(63, __float2int_ru(v * 63.0f));
    int tr = min(63, __float2int_ru(r * 63.0f));

    const int full = min(a0 + SROWS, 127) - a0;  // 32, except last strip: 31
    const float* nrow = im + (a0 + 1) * 128;

    #pragma unroll 4
    for (int it = 0; it < full; it++) {
        float nv = nrow[b];
        float nr = nrow[bp1];
        nrow += 128;

        int tnv = min(63, __float2int_ru(nv * 63.0f));
        int tnr = min(63, __float2int_ru(nr * 63.0f));

        int th = max(tv, tr);                 // h-edge bin
        int te = max(tv, tnv);                // v-edge bin
        int tf = max(th, max(tnv, tnr));      // face bin

        hcol[tv << 7] += 1;                   // vertex  (+)
        hcol[th << 7] += valH;                // h-edge  (-)
        hcol[te << 7] -= 1;                   // v-edge  (-)
        hcol[tf << 7] += valF;                // face    (+)

        tv = tnv; tr = tnr;
    }

    // tail row a=127 (last strip only): vertex + h-edge, no down cells
    if (a0 + SROWS == 128) {
        hcol[tv << 7] += 1;
        hcol[max(tv, tr) << 7] += valH;
    }
    __syncthreads();

    // reduce 128 private columns -> 64 bins (skewed, conflict-free)
    const int bin = tid & 63;
    const int p   = tid >> 6;
    int sum = 0;
    #pragma unroll 8
    for (int i = 0; i < 64; i++) {
        int c = (p << 6) + ((i + bin) & 63);
        sum += hist[(bin << 7) + c];
    }
    __syncthreads();
    hist[tid] = sum;                          // reuse hist as scratch
    __syncthreads();
    if (tid < RES)
        g_part[blockIdx.x * RES + tid] = hist[tid] + hist[RES + tid];
}

__global__ __launch_bounds__(RES)
void final_kernel(float* __restrict__ out)
{
    const int img = blockIdx.x;
    const int t = threadIdx.x;              // 64 threads
    const int base = img * STRIPS * RES + t;

    int sum = g_part[base] + g_part[base + RES]
            + g_part[base + 2 * RES] + g_part[base + 3 * RES];

    // inclusive scan: warp shuffle scan + cross-warp fixup
    const int lane = t & 31;
    #pragma unroll
    for (int s = 1; s < 32; s <<= 1) {
        int n = __shfl_up_sync(0xffffffff, sum, s);
        if (lane >= s) sum += n;
    }
    __shared__ int w0tot;
    if (t == 31) w0tot = sum;
    __syncthreads();
    if (t >= 32) sum += w0tot;

    out[img * RES + t] = (float)sum;
}

extern "C" void kernel_launch(void* const* d_in, const int* in_sizes, int n_in,
                              void* d_out, int out_size)
{
    const float* x = (const float*)d_in[0];
    float* out = (float*)d_out;
    strip_kernel<<<512 * STRIPS, NT>>>(x);
    final_kernel<<<512, RES>>>(out);
}